// round 10
// baseline (speedup 1.0000x reference)
#include <cuda_runtime.h>
#include <cuda_bf16.h>
#include <cstdint>

#define DIM     64
#define KMAX    1024
#define TM      256          // rows per CTA
#define THREADS 512          // 16 warps, 1 m-tile (16 rows) each

// ---------------- device globals (prep results) ----------------
__device__ float g_c2[KMAX];
__device__ unsigned int g_cmaxU;   // asuint(max ||c_k||), positive-float monotone
// fragment-ordered bf16 codebook image: for each n-tile (8 codes) the exact
// 8 B-fragment regs x 32 lanes the MMA needs. uint4 index = nt*64 + half*32 + lane.
__device__ __align__(16) uint4 g_cbFrag[(KMAX / 8) * 64];

// ---------------- smem layout (byte offsets) ----------------
#define OFF_A     0          // 256*128 = 32768 (bf16 swizzled A staging)
#define OFF_C2    32768      // 1024*4  = 4096   (raw c2, exact phase)
#define OFF_C2B   36864      // 1024*4  = 4096   (c2 + 0.25 bias, scan phase)
#define OFF_R2    40960      // 256*4   = 1024
#define OFF_M1    41984      // 1024
#define OFF_M2    43008      // 1024
#define OFF_M3    44032      // 1024
#define OFF_FLAG  45056      // 1024
#define OFF_NF    46080      // 16
#define SMEM_DYN  46096

#define BIAS 0.25f

__device__ __forceinline__ uint32_t smem_u32(const void* p) {
    uint32_t a;
    asm("{ .reg .u64 t; cvta.to.shared.u64 t, %1; cvt.u32.u64 %0, t; }"
        : "=r"(a) : "l"(p));
    return a;
}

// ---------------- prep: c2 (R1-exact) + fragment-ordered bf16 codebook + Cmax ----------------
__global__ void prep_kernel(const float* __restrict__ cb, int K) {
    int k = blockIdx.x * blockDim.x + threadIdx.x;
    if (k >= K) return;
    const float4* row = reinterpret_cast<const float4*>(cb + (size_t)k * DIM);
    float vals[DIM];
    float p0 = 0.f, p1 = 0.f, p2 = 0.f, p3 = 0.f;
#pragma unroll
    for (int j = 0; j < 16; j += 4) {
        float4 a = row[j + 0];
        float4 b = row[j + 1];
        float4 c = row[j + 2];
        float4 d = row[j + 3];
        p0 += a.x * a.x + a.y * a.y + a.z * a.z + a.w * a.w;
        p1 += b.x * b.x + b.y * b.y + b.z * b.z + b.w * b.w;
        p2 += c.x * c.x + c.y * c.y + c.z * c.z + c.w * c.w;
        p3 += d.x * d.x + d.y * d.y + d.z * d.z + d.w * d.w;
        vals[4*(j+0)+0]=a.x; vals[4*(j+0)+1]=a.y; vals[4*(j+0)+2]=a.z; vals[4*(j+0)+3]=a.w;
        vals[4*(j+1)+0]=b.x; vals[4*(j+1)+1]=b.y; vals[4*(j+1)+2]=b.z; vals[4*(j+1)+3]=b.w;
        vals[4*(j+2)+0]=c.x; vals[4*(j+2)+1]=c.y; vals[4*(j+2)+2]=c.z; vals[4*(j+2)+3]=c.w;
        vals[4*(j+3)+0]=d.x; vals[4*(j+3)+1]=d.y; vals[4*(j+3)+2]=d.z; vals[4*(j+3)+3]=d.w;
    }
    float c2 = (p0 + p1) + (p2 + p3);
    g_c2[k] = c2;
    atomicMax(&g_cmaxU, __float_as_uint(sqrtf(c2)));

    // Fragment image: lane l=4*i+q (i = code-in-tile) receives in b-reg j the bf16
    // pair (k-dims 8j+2q, 8j+2q+1). uint addr = nt*256 + (j>>2)*128 + l*4 + (j&3).
    const int nt = k >> 3, i = k & 7;
    unsigned int* frag = reinterpret_cast<unsigned int*>(g_cbFrag) + nt * 256;
#pragma unroll
    for (int j = 0; j < 8; j++) {
#pragma unroll
        for (int q = 0; q < 4; q++) {
            __nv_bfloat162 pr = __floats2bfloat162_rn(vals[8 * j + 2 * q],
                                                      vals[8 * j + 2 * q + 1]);
            frag[(j >> 2) * 128 + (4 * i + q) * 4 + (j & 3)] =
                *reinterpret_cast<unsigned int*>(&pr);
        }
    }
}

// ---------------- inner-step macros ----------------
#define MMA16816(d0, d1, d2, d3, ar, b0r, b1r)                                    \
    asm volatile(                                                                  \
        "mma.sync.aligned.m16n8k16.row.col.f32.bf16.bf16.f32 "                     \
        "{%0,%1,%2,%3}, {%4,%5,%6,%7}, {%8,%9}, {%0,%1,%2,%3};"                    \
        : "+f"(d0), "+f"(d1), "+f"(d2), "+f"(d3)                                   \
        : "r"((ar)[0]), "r"((ar)[1]), "r"((ar)[2]), "r"((ar)[3]),                  \
          "r"(b0r), "r"(b1r))

// insert packed value v into sorted triple (M1x,M2x,M3x)
#define MIN3(M1x, M2x, M3x, v) do {                                               \
    unsigned int t1 = umax(M1x, (v)); M1x = umin(M1x, (v));                        \
    unsigned int t2 = umax(M2x, t1);  M2x = umin(M2x, t1);                         \
    M3x = umin(M3x, t2);                                                           \
} while (0)

// merge other sorted triple (o1<=o2<=o3) into (M1x,M2x,M3x)
#define MERGE3(M1x, M2x, M3x, o1, o2, o3) do {                                     \
    unsigned int z1 = umin(M1x, (o1)), w1 = umax(M1x, (o1));                       \
    unsigned int z2 = umin(M2x, (o2)), w2 = umax(M2x, (o2));                       \
    unsigned int z3 = umin(M3x, (o3));                                             \
    M1x = z1;                                                                      \
    unsigned int q = umin(w1, z2);                                                 \
    M3x = umin(umax(w1, z2), umin(w2, z3));                                        \
    M2x = q;                                                                       \
} while (0)

#define PACKV(sv, col) ((__float_as_uint(sv) & 0xFFFFFC00u) | (unsigned int)(col))

// ---------------- main: SINGLE-pass HMMA scan with packed min-3 argmin ----------------
__global__ __launch_bounds__(THREADS, 2)
void vq_main(const float* __restrict__ residual,
             const float* __restrict__ cb,
             float* __restrict__ qout,
             float* __restrict__ codes,
             int N, int K, int wq, int wc)
{
    extern __shared__ __align__(16) unsigned char dsm[];
    const uint32_t sb = smem_u32(dsm);

    float*        sC2  = (float*)(dsm + OFF_C2);
    float*        sC2B = (float*)(dsm + OFF_C2B);
    float*        sR2  = (float*)(dsm + OFF_R2);
    unsigned int* sM1  = (unsigned int*)(dsm + OFF_M1);
    unsigned int* sM2  = (unsigned int*)(dsm + OFF_M2);
    unsigned int* sM3  = (unsigned int*)(dsm + OFF_M3);
    int*          sFlag= (int*)(dsm + OFF_FLAG);
    int*          sNF  = (int*)(dsm + OFF_NF);

    const int tid  = threadIdx.x;
    const int lane = tid & 31;
    const int warp = tid >> 5;
    const int m0   = blockIdx.x * TM;
    const int rows = (N - m0 < TM) ? (N - m0) : TM;
    const int NT   = K >> 3;

    if (tid == 0) *sNF = 0;
    for (int i = tid; i < K; i += THREADS) {
        float c2 = g_c2[i];
        sC2[i]  = c2;
        sC2B[i] = c2 + BIAS;
    }

    // --- per-row: residual -> bf16 swizzled smem + exact r2 (R1 pattern) ---
    if (tid < TM) {
        const int r = tid;
        unsigned int* aU = reinterpret_cast<unsigned int*>(dsm + OFF_A) + r * 32;
        float r2 = 0.f;
        if (r < rows) {
            const float4* rr = reinterpret_cast<const float4*>(residual + (size_t)(m0 + r) * DIM);
            float p0 = 0.f, p1 = 0.f, p2 = 0.f, p3 = 0.f;
#pragma unroll
            for (int j = 0; j < 16; j++) {
                float4 v = rr[j];
                p0 += v.x * v.x;
                p1 += v.y * v.y;
                p2 += v.z * v.z;
                p3 += v.w * v.w;
                __nv_bfloat162 h0 = __floats2bfloat162_rn(v.x, v.y);
                __nv_bfloat162 h1 = __floats2bfloat162_rn(v.z, v.w);
                int j0 = 2 * j, j1 = 2 * j + 1;
                aU[(((j0 >> 2) ^ (r & 7)) << 2) + (j0 & 3)] = *reinterpret_cast<unsigned int*>(&h0);
                aU[(((j1 >> 2) ^ (r & 7)) << 2) + (j1 & 3)] = *reinterpret_cast<unsigned int*>(&h1);
            }
            r2 = (p0 + p1) + (p2 + p3);
        } else {
#pragma unroll
            for (int j = 0; j < 32; j++) aU[j] = 0;
        }
        sR2[r] = r2;
    }
    __syncthreads();

    // --- A fragments (resident): 1 m-tile x 4 k-chunks, swizzled ldmatrix.x4 ---
    uint32_t a[4][4];
    {
        const uint32_t rowb = (uint32_t)(warp * 16 + (lane & 15)) * 128u;
#pragma unroll
        for (int kc = 0; kc < 4; kc++) {
            uint32_t phys = (uint32_t)((2 * kc + (lane >> 4)) ^ (lane & 7));
            uint32_t ad = sb + OFF_A + rowb + (phys << 4);
            asm volatile("ldmatrix.sync.aligned.m8n8.x4.shared.b16 {%0,%1,%2,%3}, [%4];"
                : "=r"(a[kc][0]), "=r"(a[kc][1]), "=r"(a[kc][2]), "=r"(a[kc][3])
                : "r"(ad));
        }
    }

    const uint4* bp = g_cbFrag + lane;          // per-lane fragment stream
    const float* c2Bp = sC2B + ((lane & 3) << 1);
    const int rA0 = warp * 16 + (lane >> 2);    // slot rows: rA0 and rA0+8
    const unsigned int lcb = (unsigned int)((lane & 3) << 1);

    // ================= single pass: packed min-3 of s_b = (c2+BIAS) - 2*dot~ =================
    unsigned int A1 = 0xFFFFFFFFu, A2 = 0xFFFFFFFFu, A3 = 0xFFFFFFFFu;  // row rA0
    unsigned int B1 = 0xFFFFFFFFu, B2 = 0xFFFFFFFFu, B3 = 0xFFFFFFFFu;  // row rA0+8

    for (int nt = 0; nt < NT; nt++) {
        uint4 c0 = bp[nt * 64], c1 = bp[nt * 64 + 32];
        const float2 c2v = *reinterpret_cast<const float2*>(c2Bp + (nt << 3));
        float e0 = 0.f, e1 = 0.f, e2 = 0.f, e3 = 0.f;
        float f0 = 0.f, f1 = 0.f, f2 = 0.f, f3 = 0.f;
        MMA16816(e0, e1, e2, e3, a[0], c0.x, c0.y);
        MMA16816(f0, f1, f2, f3, a[2], c1.x, c1.y);
        MMA16816(e0, e1, e2, e3, a[1], c0.z, c0.w);
        MMA16816(f0, f1, f2, f3, a[3], c1.z, c1.w);
        const unsigned int col = (unsigned int)(nt << 3) + lcb;
        float s;
        s = __fmaf_rn(__fadd_rn(e0, f0), -2.0f, c2v.x); MIN3(A1, A2, A3, PACKV(s, col));
        s = __fmaf_rn(__fadd_rn(e1, f1), -2.0f, c2v.y); MIN3(A1, A2, A3, PACKV(s, col + 1));
        s = __fmaf_rn(__fadd_rn(e2, f2), -2.0f, c2v.x); MIN3(B1, B2, B3, PACKV(s, col));
        s = __fmaf_rn(__fadd_rn(e3, f3), -2.0f, c2v.y); MIN3(B1, B2, B3, PACKV(s, col + 1));
    }

    // --- quad-merge min-3 across the 4 lanes covering each row ---
#pragma unroll
    for (int st = 1; st <= 2; st <<= 1) {
        unsigned int o1 = __shfl_xor_sync(0xFFFFFFFFu, A1, st);
        unsigned int o2 = __shfl_xor_sync(0xFFFFFFFFu, A2, st);
        unsigned int o3 = __shfl_xor_sync(0xFFFFFFFFu, A3, st);
        MERGE3(A1, A2, A3, o1, o2, o3);
        o1 = __shfl_xor_sync(0xFFFFFFFFu, B1, st);
        o2 = __shfl_xor_sync(0xFFFFFFFFu, B2, st);
        o3 = __shfl_xor_sync(0xFFFFFFFFu, B3, st);
        MERGE3(B1, B2, B3, o1, o2, o3);
    }
    if ((lane & 3) == 0) {
        sM1[rA0] = A1; sM2[rA0] = A2; sM3[rA0] = A3;
        sM1[rA0 + 8] = B1; sM2[rA0 + 8] = B2; sM3[rA0 + 8] = B3;
    }
    __syncthreads();

    // ================= per-row decision =================
    const float CmaxC = __uint_as_float(g_cmaxU) * 0.018f;
    const int t = tid;
    if (t < rows) {
        const unsigned int u1 = sM1[t], u2 = sM2[t], u3 = sM3[t];
        const float f1 = __uint_as_float(u1 & 0xFFFFFC00u);
        const float f2 = __uint_as_float(u2 & 0xFFFFFC00u);
        const float f3 = __uint_as_float(u3 & 0xFFFFFC00u);
        const float r2 = sR2[t];
        const float th = sqrtf(r2) * CmaxC + 1.5e-4f;
        int bestK = -1;
        if (f2 - f1 > th) {
            bestK = (int)(u1 & 1023u);               // unique in window => argmin
        } else if (f3 - f1 > th) {
            // exactly 2 candidates: exact fp32 recheck (R1 math, lexicographic)
            const int k1 = (int)(u1 & 1023u), k2 = (int)(u2 & 1023u);
            const float4* rr = reinterpret_cast<const float4*>(residual + (size_t)(m0 + t) * DIM);
            const float4* c1p = reinterpret_cast<const float4*>(cb + (size_t)k1 * DIM);
            const float4* c2p = reinterpret_cast<const float4*>(cb + (size_t)k2 * DIM);
            float a1 = 0.f, a2 = 0.f;
#pragma unroll
            for (int j = 0; j < 16; j++) {
                float4 rv = rr[j];
                float4 v1 = c1p[j];
                float4 v2 = c2p[j];
                a1 += rv.x * v1.x; a1 += rv.y * v1.y; a1 += rv.z * v1.z; a1 += rv.w * v1.w;
                a2 += rv.x * v2.x; a2 += rv.y * v2.y; a2 += rv.z * v2.z; a2 += rv.w * v2.w;
            }
            float d1 = (r2 + sC2[k1]) - 2.0f * a1;
            float d2 = (r2 + sC2[k2]) - 2.0f * a2;
            bestK = (d2 < d1 || (d2 == d1 && k2 < k1)) ? k2 : k1;
        } else {
            int idx = atomicAdd(sNF, 1);
            sFlag[idx] = t;
        }
        if (bestK >= 0) {
            const int n = m0 + t;
            if (wc) codes[n] = (float)bestK;
            if (wq) {
                const float4* brow = reinterpret_cast<const float4*>(cb + (size_t)bestK * DIM);
                float4* qo = reinterpret_cast<float4*>(qout + (size_t)n * DIM);
#pragma unroll
                for (int j = 0; j < 16; j++) qo[j] = brow[j];
            }
        }
    }
    __syncthreads();

    // ================= cooperative exact rescan for flagged rows (rare) =================
    const int nf = *sNF;
    for (int i = warp; i < nf; i += 16) {
        const int row = sFlag[i];
        const int n = m0 + row;
        const float r2 = sR2[row];
        float r[DIM];
        {
            const float4* rr = reinterpret_cast<const float4*>(residual + (size_t)n * DIM);
#pragma unroll
            for (int j = 0; j < 16; j++) {
                float4 v = rr[j];
                r[4 * j + 0] = v.x; r[4 * j + 1] = v.y;
                r[4 * j + 2] = v.z; r[4 * j + 3] = v.w;
            }
        }
        float best = 3.402823466e+38f;
        int bestK = 0x7FFFFFFF;
        for (int k = lane; k < K; k += 32) {
            const float4* c4 = reinterpret_cast<const float4*>(cb + (size_t)k * DIM);
            float a0 = 0.f;
#pragma unroll
            for (int j = 0; j < 16; j++) {
                float4 v = c4[j];
                a0 += r[4 * j + 0] * v.x;
                a0 += r[4 * j + 1] * v.y;
                a0 += r[4 * j + 2] * v.z;
                a0 += r[4 * j + 3] * v.w;
            }
            float d = (r2 + sC2[k]) - 2.0f * a0;
            if (d < best || (d == best && k < bestK)) { best = d; bestK = k; }
        }
#pragma unroll
        for (int off = 16; off >= 1; off >>= 1) {
            float ob = __shfl_xor_sync(0xFFFFFFFFu, best, off);
            int   ok = __shfl_xor_sync(0xFFFFFFFFu, bestK, off);
            if (ob < best || (ob == best && ok < bestK)) { best = ob; bestK = ok; }
        }
        if (wc && lane == 0) codes[n] = (float)bestK;
        if (wq && lane < 16) {
            const float4* brow = reinterpret_cast<const float4*>(cb + (size_t)bestK * DIM);
            reinterpret_cast<float4*>(qout + (size_t)n * DIM)[lane] = brow[lane];
        }
    }
}

// ---------------- launch ----------------
extern "C" void kernel_launch(void* const* d_in, const int* in_sizes, int n_in,
                              void* d_out, int out_size)
{
    const float* residual = (const float*)d_in[0];
    const float* cb       = (const float*)d_in[1];
    const int N = in_sizes[0] / DIM;
    const int K = in_sizes[1] / DIM;

    float* out = (float*)d_out;
    int write_q = 0, write_codes = 0;
    float* qout = out;
    float* codes = out;
    if (out_size >= N * DIM + N) {
        write_q = 1; write_codes = 1;
        codes = out + (size_t)N * DIM;
    } else if (out_size >= N * DIM) {
        write_q = 1;
    } else {
        write_codes = 1;
    }

    cudaFuncSetAttribute(vq_main, cudaFuncAttributeMaxDynamicSharedMemorySize, SMEM_DYN);

    prep_kernel<<<(K + 255) / 256, 256>>>(cb, K);

    int blocks = (N + TM - 1) / TM;
    vq_main<<<blocks, THREADS, SMEM_DYN>>>(residual, cb, qout, codes,
                                           N, K, write_q, write_codes);
}

// round 11
// speedup vs baseline: 1.0342x; 1.0342x over previous
#include <cuda_runtime.h>
#include <cuda_bf16.h>
#include <cstdint>

#define DIM     64
#define KMAX    1024
#define TM      512          // rows per CTA
#define THREADS 512          // 16 warps x 2 m-tiles = 32 rows per warp

// ---------------- device globals (prep results) ----------------
__device__ float g_c2[KMAX];
__device__ unsigned int g_cmaxU;   // asuint(max ||c_k||), positive-float monotone
// fragment-ordered bf16 codebook image: for each n-tile (8 codes) the exact
// 8 B-fragment regs x 32 lanes the MMA needs. uint4 index = nt*64 + half*32 + lane.
__device__ __align__(16) uint4 g_cbFrag[(KMAX / 8) * 64];

// ---------------- smem layout (byte offsets) ----------------
#define OFF_A     0          // 512*128 = 65536 (bf16 swizzled A staging)
#define OFF_C2    65536      // 4096   (raw c2, exact phase)
#define OFF_C2B   69632      // 4096   (c2 + 0.25 bias, scan phase)
#define OFF_R2    73728      // 2048
#define OFF_M1    75776      // 2048
#define OFF_M2    77824      // 2048
#define OFF_M3    79872      // 2048
#define OFF_FLAG  81920      // 2048
#define OFF_NF    83968      // 16
#define SMEM_DYN  83984

#define BIAS 0.25f

__device__ __forceinline__ uint32_t smem_u32(const void* p) {
    uint32_t a;
    asm("{ .reg .u64 t; cvta.to.shared.u64 t, %1; cvt.u32.u64 %0, t; }"
        : "=r"(a) : "l"(p));
    return a;
}

// ---------------- prep: c2 (R1-exact) + fragment-ordered bf16 codebook + Cmax ----------------
__global__ void prep_kernel(const float* __restrict__ cb, int K) {
    int k = blockIdx.x * blockDim.x + threadIdx.x;
    if (k >= K) return;
    const float4* row = reinterpret_cast<const float4*>(cb + (size_t)k * DIM);
    float vals[DIM];
    float p0 = 0.f, p1 = 0.f, p2 = 0.f, p3 = 0.f;
#pragma unroll
    for (int j = 0; j < 16; j += 4) {
        float4 a = row[j + 0];
        float4 b = row[j + 1];
        float4 c = row[j + 2];
        float4 d = row[j + 3];
        p0 += a.x * a.x + a.y * a.y + a.z * a.z + a.w * a.w;
        p1 += b.x * b.x + b.y * b.y + b.z * b.z + b.w * b.w;
        p2 += c.x * c.x + c.y * c.y + c.z * c.z + c.w * c.w;
        p3 += d.x * d.x + d.y * d.y + d.z * d.z + d.w * d.w;
        vals[4*(j+0)+0]=a.x; vals[4*(j+0)+1]=a.y; vals[4*(j+0)+2]=a.z; vals[4*(j+0)+3]=a.w;
        vals[4*(j+1)+0]=b.x; vals[4*(j+1)+1]=b.y; vals[4*(j+1)+2]=b.z; vals[4*(j+1)+3]=b.w;
        vals[4*(j+2)+0]=c.x; vals[4*(j+2)+1]=c.y; vals[4*(j+2)+2]=c.z; vals[4*(j+2)+3]=c.w;
        vals[4*(j+3)+0]=d.x; vals[4*(j+3)+1]=d.y; vals[4*(j+3)+2]=d.z; vals[4*(j+3)+3]=d.w;
    }
    float c2 = (p0 + p1) + (p2 + p3);
    g_c2[k] = c2;
    atomicMax(&g_cmaxU, __float_as_uint(sqrtf(c2)));

    // Fragment image: lane l=4*i+q (i = code-in-tile) receives in b-reg j the bf16
    // pair (k-dims 8j+2q, 8j+2q+1). uint addr = nt*256 + (j>>2)*128 + l*4 + (j&3).
    const int nt = k >> 3, i = k & 7;
    unsigned int* frag = reinterpret_cast<unsigned int*>(g_cbFrag) + nt * 256;
#pragma unroll
    for (int j = 0; j < 8; j++) {
#pragma unroll
        for (int q = 0; q < 4; q++) {
            __nv_bfloat162 pr = __floats2bfloat162_rn(vals[8 * j + 2 * q],
                                                      vals[8 * j + 2 * q + 1]);
            frag[(j >> 2) * 128 + (4 * i + q) * 4 + (j & 3)] =
                *reinterpret_cast<unsigned int*>(&pr);
        }
    }
}

// ---------------- inner-step macros ----------------
#define MMA16816(d0, d1, d2, d3, ar, b0r, b1r)                                    \
    asm volatile(                                                                  \
        "mma.sync.aligned.m16n8k16.row.col.f32.bf16.bf16.f32 "                     \
        "{%0,%1,%2,%3}, {%4,%5,%6,%7}, {%8,%9}, {%0,%1,%2,%3};"                    \
        : "+f"(d0), "+f"(d1), "+f"(d2), "+f"(d3)                                   \
        : "r"((ar)[0]), "r"((ar)[1]), "r"((ar)[2]), "r"((ar)[3]),                  \
          "r"(b0r), "r"(b1r))

// insert packed value v into sorted triple (M1x,M2x,M3x)
#define MIN3(M1x, M2x, M3x, v) do {                                               \
    unsigned int t1 = umax(M1x, (v)); M1x = umin(M1x, (v));                        \
    unsigned int t2 = umax(M2x, t1);  M2x = umin(M2x, t1);                         \
    M3x = umin(M3x, t2);                                                           \
} while (0)

// merge other sorted triple (o1<=o2<=o3) into (M1x,M2x,M3x)
#define MERGE3(M1x, M2x, M3x, o1, o2, o3) do {                                     \
    unsigned int z1 = umin(M1x, (o1)), w1 = umax(M1x, (o1));                       \
    unsigned int z2 = umin(M2x, (o2)), w2 = umax(M2x, (o2));                       \
    unsigned int z3 = umin(M3x, (o3));                                             \
    M1x = z1;                                                                      \
    unsigned int q = umin(w1, z2);                                                 \
    M3x = umin(umax(w1, z2), umin(w2, z3));                                        \
    M2x = q;                                                                       \
} while (0)

#define PACKV(sv, col) ((__float_as_uint(sv) & 0xFFFFFC00u) | (unsigned int)(col))

// one m-tile (4 MMAs, 2 independent chains) -> 4 s-values -> two min3 slots
#define MT_STEP(amt, P1, P2, P3, Q1, Q2, Q3) do {                                  \
    float e0 = 0.f, e1 = 0.f, e2 = 0.f, e3 = 0.f;                                  \
    float f0 = 0.f, f1 = 0.f, f2 = 0.f, f3 = 0.f;                                  \
    MMA16816(e0, e1, e2, e3, (amt)[0], c0.x, c0.y);                                \
    MMA16816(f0, f1, f2, f3, (amt)[2], c1.x, c1.y);                                \
    MMA16816(e0, e1, e2, e3, (amt)[1], c0.z, c0.w);                                \
    MMA16816(f0, f1, f2, f3, (amt)[3], c1.z, c1.w);                                \
    float s;                                                                       \
    s = __fmaf_rn(__fadd_rn(e0, f0), -2.0f, c2v.x); MIN3(P1, P2, P3, PACKV(s, col));       \
    s = __fmaf_rn(__fadd_rn(e1, f1), -2.0f, c2v.y); MIN3(P1, P2, P3, PACKV(s, col + 1));   \
    s = __fmaf_rn(__fadd_rn(e2, f2), -2.0f, c2v.x); MIN3(Q1, Q2, Q3, PACKV(s, col));       \
    s = __fmaf_rn(__fadd_rn(e3, f3), -2.0f, c2v.y); MIN3(Q1, Q2, Q3, PACKV(s, col + 1));   \
} while (0)

// ---------------- main: SINGLE-pass HMMA scan, 2 m-tiles/warp, packed min-3 ----------------
__global__ __launch_bounds__(THREADS, 1)
void vq_main(const float* __restrict__ residual,
             const float* __restrict__ cb,
             float* __restrict__ qout,
             float* __restrict__ codes,
             int N, int K, int wq, int wc)
{
    extern __shared__ __align__(16) unsigned char dsm[];
    const uint32_t sb = smem_u32(dsm);

    float*        sC2  = (float*)(dsm + OFF_C2);
    float*        sC2B = (float*)(dsm + OFF_C2B);
    float*        sR2  = (float*)(dsm + OFF_R2);
    unsigned int* sM1  = (unsigned int*)(dsm + OFF_M1);
    unsigned int* sM2  = (unsigned int*)(dsm + OFF_M2);
    unsigned int* sM3  = (unsigned int*)(dsm + OFF_M3);
    int*          sFlag= (int*)(dsm + OFF_FLAG);
    int*          sNF  = (int*)(dsm + OFF_NF);

    const int tid  = threadIdx.x;
    const int lane = tid & 31;
    const int warp = tid >> 5;
    const int m0   = blockIdx.x * TM;
    const int rows = (N - m0 < TM) ? (N - m0) : TM;
    const int NT   = K >> 3;

    if (tid == 0) *sNF = 0;
    for (int i = tid; i < K; i += THREADS) {
        float c2 = g_c2[i];
        sC2[i]  = c2;
        sC2B[i] = c2 + BIAS;
    }

    // --- per-row: residual -> bf16 swizzled smem + exact r2 (R1 pattern) ---
    {
        const int r = tid;
        unsigned int* aU = reinterpret_cast<unsigned int*>(dsm + OFF_A) + r * 32;
        float r2 = 0.f;
        if (r < rows) {
            const float4* rr = reinterpret_cast<const float4*>(residual + (size_t)(m0 + r) * DIM);
            float p0 = 0.f, p1 = 0.f, p2 = 0.f, p3 = 0.f;
#pragma unroll
            for (int j = 0; j < 16; j++) {
                float4 v = rr[j];
                p0 += v.x * v.x;
                p1 += v.y * v.y;
                p2 += v.z * v.z;
                p3 += v.w * v.w;
                __nv_bfloat162 h0 = __floats2bfloat162_rn(v.x, v.y);
                __nv_bfloat162 h1 = __floats2bfloat162_rn(v.z, v.w);
                int j0 = 2 * j, j1 = 2 * j + 1;
                aU[(((j0 >> 2) ^ (r & 7)) << 2) + (j0 & 3)] = *reinterpret_cast<unsigned int*>(&h0);
                aU[(((j1 >> 2) ^ (r & 7)) << 2) + (j1 & 3)] = *reinterpret_cast<unsigned int*>(&h1);
            }
            r2 = (p0 + p1) + (p2 + p3);
        } else {
#pragma unroll
            for (int j = 0; j < 32; j++) aU[j] = 0;
        }
        sR2[r] = r2;
    }
    __syncthreads();

    // --- A fragments (resident): 2 m-tiles x 4 k-chunks, swizzled ldmatrix.x4 ---
    uint32_t a[2][4][4];
#pragma unroll
    for (int mt = 0; mt < 2; mt++) {
        const uint32_t rowb = (uint32_t)(warp * 32 + mt * 16 + (lane & 15)) * 128u;
#pragma unroll
        for (int kc = 0; kc < 4; kc++) {
            uint32_t phys = (uint32_t)((2 * kc + (lane >> 4)) ^ (lane & 7));
            uint32_t ad = sb + OFF_A + rowb + (phys << 4);
            asm volatile("ldmatrix.sync.aligned.m8n8.x4.shared.b16 {%0,%1,%2,%3}, [%4];"
                : "=r"(a[mt][kc][0]), "=r"(a[mt][kc][1]),
                  "=r"(a[mt][kc][2]), "=r"(a[mt][kc][3])
                : "r"(ad));
        }
    }

    const uint4* bp = g_cbFrag + lane;          // per-lane fragment stream
    const float* c2Bp = sC2B + ((lane & 3) << 1);
    const int rA0 = warp * 32 + (lane >> 2);    // slot rows: rA0, +8, +16, +24
    const unsigned int lcb = (unsigned int)((lane & 3) << 1);

    // ================= single pass: packed min-3 of s_b = (c2+BIAS) - 2*dot~ =================
    unsigned int A1 = 0xFFFFFFFFu, A2 = 0xFFFFFFFFu, A3 = 0xFFFFFFFFu;  // rA0
    unsigned int B1 = 0xFFFFFFFFu, B2 = 0xFFFFFFFFu, B3 = 0xFFFFFFFFu;  // rA0+8
    unsigned int C1 = 0xFFFFFFFFu, C2 = 0xFFFFFFFFu, C3 = 0xFFFFFFFFu;  // rA0+16
    unsigned int D1 = 0xFFFFFFFFu, D2 = 0xFFFFFFFFu, D3 = 0xFFFFFFFFu;  // rA0+24

    {
        uint4 c0 = bp[0], c1 = bp[32];
        for (int nt = 0; nt < NT; nt++) {
            const int ntn = (nt + 1 < NT) ? nt + 1 : nt;
            uint4 n0 = bp[ntn * 64], n1 = bp[ntn * 64 + 32];
            const float2 c2v = *reinterpret_cast<const float2*>(c2Bp + (nt << 3));
            const unsigned int col = (unsigned int)(nt << 3) + lcb;
            MT_STEP(a[0], A1, A2, A3, B1, B2, B3);
            MT_STEP(a[1], C1, C2, C3, D1, D2, D3);
            c0 = n0; c1 = n1;
        }
    }

    // --- quad-merge min-3 across the 4 lanes covering each row ---
#pragma unroll
    for (int st = 1; st <= 2; st <<= 1) {
        unsigned int o1, o2, o3;
        o1 = __shfl_xor_sync(0xFFFFFFFFu, A1, st);
        o2 = __shfl_xor_sync(0xFFFFFFFFu, A2, st);
        o3 = __shfl_xor_sync(0xFFFFFFFFu, A3, st);
        MERGE3(A1, A2, A3, o1, o2, o3);
        o1 = __shfl_xor_sync(0xFFFFFFFFu, B1, st);
        o2 = __shfl_xor_sync(0xFFFFFFFFu, B2, st);
        o3 = __shfl_xor_sync(0xFFFFFFFFu, B3, st);
        MERGE3(B1, B2, B3, o1, o2, o3);
        o1 = __shfl_xor_sync(0xFFFFFFFFu, C1, st);
        o2 = __shfl_xor_sync(0xFFFFFFFFu, C2, st);
        o3 = __shfl_xor_sync(0xFFFFFFFFu, C3, st);
        MERGE3(C1, C2, C3, o1, o2, o3);
        o1 = __shfl_xor_sync(0xFFFFFFFFu, D1, st);
        o2 = __shfl_xor_sync(0xFFFFFFFFu, D2, st);
        o3 = __shfl_xor_sync(0xFFFFFFFFu, D3, st);
        MERGE3(D1, D2, D3, o1, o2, o3);
    }
    if ((lane & 3) == 0) {
        sM1[rA0]      = A1; sM2[rA0]      = A2; sM3[rA0]      = A3;
        sM1[rA0 + 8]  = B1; sM2[rA0 + 8]  = B2; sM3[rA0 + 8]  = B3;
        sM1[rA0 + 16] = C1; sM2[rA0 + 16] = C2; sM3[rA0 + 16] = C3;
        sM1[rA0 + 24] = D1; sM2[rA0 + 24] = D2; sM3[rA0 + 24] = D3;
    }
    __syncthreads();

    // ================= per-row decision =================
    const float CmaxC = __uint_as_float(g_cmaxU) * 0.018f;
    const int t = tid;
    if (t < rows) {
        const unsigned int u1 = sM1[t], u2 = sM2[t], u3 = sM3[t];
        const float f1 = __uint_as_float(u1 & 0xFFFFFC00u);
        const float f2 = __uint_as_float(u2 & 0xFFFFFC00u);
        const float f3 = __uint_as_float(u3 & 0xFFFFFC00u);
        const float r2 = sR2[t];
        const float th = sqrtf(r2) * CmaxC + 1.5e-4f;
        int bestK = -1;
        if (f2 - f1 > th) {
            bestK = (int)(u1 & 1023u);               // unique in window => argmin
        } else if (f3 - f1 > th) {
            // exactly 2 candidates: exact fp32 recheck (R1 math, lexicographic)
            const int k1 = (int)(u1 & 1023u), k2 = (int)(u2 & 1023u);
            const float4* rr = reinterpret_cast<const float4*>(residual + (size_t)(m0 + t) * DIM);
            const float4* c1p = reinterpret_cast<const float4*>(cb + (size_t)k1 * DIM);
            const float4* c2p = reinterpret_cast<const float4*>(cb + (size_t)k2 * DIM);
            float a1 = 0.f, a2 = 0.f;
#pragma unroll
            for (int j = 0; j < 16; j++) {
                float4 rv = rr[j];
                float4 v1 = c1p[j];
                float4 v2 = c2p[j];
                a1 += rv.x * v1.x; a1 += rv.y * v1.y; a1 += rv.z * v1.z; a1 += rv.w * v1.w;
                a2 += rv.x * v2.x; a2 += rv.y * v2.y; a2 += rv.z * v2.z; a2 += rv.w * v2.w;
            }
            float d1 = (r2 + sC2[k1]) - 2.0f * a1;
            float d2 = (r2 + sC2[k2]) - 2.0f * a2;
            bestK = (d2 < d1 || (d2 == d1 && k2 < k1)) ? k2 : k1;
        } else {
            int idx = atomicAdd(sNF, 1);
            sFlag[idx] = t;
        }
        if (bestK >= 0) {
            const int n = m0 + t;
            if (wc) codes[n] = (float)bestK;
            if (wq) {
                const float4* brow = reinterpret_cast<const float4*>(cb + (size_t)bestK * DIM);
                float4* qo = reinterpret_cast<float4*>(qout + (size_t)n * DIM);
#pragma unroll
                for (int j = 0; j < 16; j++) qo[j] = brow[j];
            }
        }
    }
    __syncthreads();

    // ================= cooperative exact rescan for flagged rows (rare) =================
    const int nf = *sNF;
    for (int i = warp; i < nf; i += 16) {
        const int row = sFlag[i];
        const int n = m0 + row;
        const float r2 = sR2[row];
        float r[DIM];
        {
            const float4* rr = reinterpret_cast<const float4*>(residual + (size_t)n * DIM);
#pragma unroll
            for (int j = 0; j < 16; j++) {
                float4 v = rr[j];
                r[4 * j + 0] = v.x; r[4 * j + 1] = v.y;
                r[4 * j + 2] = v.z; r[4 * j + 3] = v.w;
            }
        }
        float best = 3.402823466e+38f;
        int bestK = 0x7FFFFFFF;
        for (int k = lane; k < K; k += 32) {
            const float4* c4 = reinterpret_cast<const float4*>(cb + (size_t)k * DIM);
            float a0 = 0.f;
#pragma unroll
            for (int j = 0; j < 16; j++) {
                float4 v = c4[j];
                a0 += r[4 * j + 0] * v.x;
                a0 += r[4 * j + 1] * v.y;
                a0 += r[4 * j + 2] * v.z;
                a0 += r[4 * j + 3] * v.w;
            }
            float d = (r2 + sC2[k]) - 2.0f * a0;
            if (d < best || (d == best && k < bestK)) { best = d; bestK = k; }
        }
#pragma unroll
        for (int off = 16; off >= 1; off >>= 1) {
            float ob = __shfl_xor_sync(0xFFFFFFFFu, best, off);
            int   ok = __shfl_xor_sync(0xFFFFFFFFu, bestK, off);
            if (ob < best || (ob == best && ok < bestK)) { best = ob; bestK = ok; }
        }
        if (wc && lane == 0) codes[n] = (float)bestK;
        if (wq && lane < 16) {
            const float4* brow = reinterpret_cast<const float4*>(cb + (size_t)bestK * DIM);
            reinterpret_cast<float4*>(qout + (size_t)n * DIM)[lane] = brow[lane];
        }
    }
}

// ---------------- launch ----------------
extern "C" void kernel_launch(void* const* d_in, const int* in_sizes, int n_in,
                              void* d_out, int out_size)
{
    const float* residual = (const float*)d_in[0];
    const float* cb       = (const float*)d_in[1];
    const int N = in_sizes[0] / DIM;
    const int K = in_sizes[1] / DIM;

    float* out = (float*)d_out;
    int write_q = 0, write_codes = 0;
    float* qout = out;
    float* codes = out;
    if (out_size >= N * DIM + N) {
        write_q = 1; write_codes = 1;
        codes = out + (size_t)N * DIM;
    } else if (out_size >= N * DIM) {
        write_q = 1;
    } else {
        write_codes = 1;
    }

    cudaFuncSetAttribute(vq_main, cudaFuncAttributeMaxDynamicSharedMemorySize, SMEM_DYN);

    prep_kernel<<<(K + 255) / 256, 256>>>(cb, K);

    int blocks = (N + TM - 1) / TM;
    vq_main<<<blocks, THREADS, SMEM_DYN>>>(residual, cb, qout, codes,
                                           N, K, write_q, write_codes);
}

// round 12
// speedup vs baseline: 5.1993x; 5.0273x over previous
#include <cuda_runtime.h>
#include <cuda_bf16.h>
#include <cstdint>

#define DIM     64
#define KMAX    1024
#define TM      512          // rows per CTA
#define THREADS 512          // 16 warps x 2 m-tiles = 32 rows per warp
#define CAP     16

// ---------------- device globals (prep results) ----------------
__device__ float g_c2[KMAX];
__device__ unsigned int g_cmaxU;   // asuint(max ||c_k||), positive-float monotone
// fragment-ordered bf16 codebook image: for each n-tile (8 codes) the exact
// 8 B-fragment regs x 32 lanes the MMA needs. uint4 index = nt*64 + half*32 + lane.
__device__ __align__(16) uint4 g_cbFrag[(KMAX / 8) * 64];

// ---------------- smem layout (byte offsets) ----------------
#define OFF_A     0          // 512*128 = 65536 (bf16 swizzled A staging)
#define OFF_C2    65536      // 4096
#define OFF_R2    69632      // 2048
#define OFF_CNT   71680      // 2048
#define OFF_CAND  73728      // 512*16*2 = 16384
#define SMEM_DYN  90112

__device__ __forceinline__ uint32_t smem_u32(const void* p) {
    uint32_t a;
    asm("{ .reg .u64 t; cvta.to.shared.u64 t, %1; cvt.u32.u64 %0, t; }"
        : "=r"(a) : "l"(p));
    return a;
}

// ---------------- prep: c2 (R1-exact) + fragment-ordered bf16 codebook + Cmax ----------------
__global__ void prep_kernel(const float* __restrict__ cb, int K) {
    int k = blockIdx.x * blockDim.x + threadIdx.x;
    if (k >= K) return;
    const float4* row = reinterpret_cast<const float4*>(cb + (size_t)k * DIM);
    float vals[DIM];
    float p0 = 0.f, p1 = 0.f, p2 = 0.f, p3 = 0.f;
#pragma unroll
    for (int j = 0; j < 16; j += 4) {
        float4 a = row[j + 0];
        float4 b = row[j + 1];
        float4 c = row[j + 2];
        float4 d = row[j + 3];
        p0 += a.x * a.x + a.y * a.y + a.z * a.z + a.w * a.w;
        p1 += b.x * b.x + b.y * b.y + b.z * b.z + b.w * b.w;
        p2 += c.x * c.x + c.y * c.y + c.z * c.z + c.w * c.w;
        p3 += d.x * d.x + d.y * d.y + d.z * d.z + d.w * d.w;
        vals[4*(j+0)+0]=a.x; vals[4*(j+0)+1]=a.y; vals[4*(j+0)+2]=a.z; vals[4*(j+0)+3]=a.w;
        vals[4*(j+1)+0]=b.x; vals[4*(j+1)+1]=b.y; vals[4*(j+1)+2]=b.z; vals[4*(j+1)+3]=b.w;
        vals[4*(j+2)+0]=c.x; vals[4*(j+2)+1]=c.y; vals[4*(j+2)+2]=c.z; vals[4*(j+2)+3]=c.w;
        vals[4*(j+3)+0]=d.x; vals[4*(j+3)+1]=d.y; vals[4*(j+3)+2]=d.z; vals[4*(j+3)+3]=d.w;
    }
    float c2 = (p0 + p1) + (p2 + p3);
    g_c2[k] = c2;
    atomicMax(&g_cmaxU, __float_as_uint(sqrtf(c2)));

    // Fragment image: lane l=4*i+q (i = code-in-tile) receives in b-reg j the bf16
    // pair (k-dims 8j+2q, 8j+2q+1). uint addr = nt*256 + (j>>2)*128 + l*4 + (j&3).
    const int nt = k >> 3, i = k & 7;
    unsigned int* frag = reinterpret_cast<unsigned int*>(g_cbFrag) + nt * 256;
#pragma unroll
    for (int j = 0; j < 8; j++) {
#pragma unroll
        for (int q = 0; q < 4; q++) {
            __nv_bfloat162 pr = __floats2bfloat162_rn(vals[8 * j + 2 * q],
                                                      vals[8 * j + 2 * q + 1]);
            frag[(j >> 2) * 128 + (4 * i + q) * 4 + (j & 3)] =
                *reinterpret_cast<unsigned int*>(&pr);
        }
    }
}

// ---------------- inner-step macros ----------------
#define MMA16816(d0, d1, d2, d3, ar, b0r, b1r)                                    \
    asm volatile(                                                                  \
        "mma.sync.aligned.m16n8k16.row.col.f32.bf16.bf16.f32 "                     \
        "{%0,%1,%2,%3}, {%4,%5,%6,%7}, {%8,%9}, {%0,%1,%2,%3};"                    \
        : "+f"(d0), "+f"(d1), "+f"(d2), "+f"(d3)                                   \
        : "r"((ar)[0]), "r"((ar)[1]), "r"((ar)[2]), "r"((ar)[3]),                  \
          "r"(b0r), "r"(b1r))

// one m-tile: 4 MMAs in 2 independent chains -> s0..s3 (bitwise-stable form)
#define MT_S(amt) do {                                                             \
    float e0 = 0.f, e1 = 0.f, e2 = 0.f, e3 = 0.f;                                  \
    float f0 = 0.f, f1 = 0.f, f2 = 0.f, f3 = 0.f;                                  \
    MMA16816(e0, e1, e2, e3, (amt)[0], c0.x, c0.y);                                \
    MMA16816(f0, f1, f2, f3, (amt)[2], c1.x, c1.y);                                \
    MMA16816(e0, e1, e2, e3, (amt)[1], c0.z, c0.w);                                \
    MMA16816(f0, f1, f2, f3, (amt)[3], c1.z, c1.w);                                \
    s0 = __fmaf_rn(__fadd_rn(e0, f0), -2.0f, c2v.x);                               \
    s1 = __fmaf_rn(__fadd_rn(e1, f1), -2.0f, c2v.y);                               \
    s2 = __fmaf_rn(__fadd_rn(e2, f2), -2.0f, c2v.x);                               \
    s3 = __fmaf_rn(__fadd_rn(e3, f3), -2.0f, c2v.y);                               \
} while (0)

#define APPEND(rr, kk) do {                                                        \
    int c = atomicAdd(&sCNT[(rr)], 1);                                             \
    if (c < CAP) sCand[(rr) * CAP + c] = (unsigned short)(kk);                     \
} while (0)

// ---------------- main: two-pass HMMA, LDG fragment stream, 2 m-tiles/warp ----------------
__global__ __launch_bounds__(THREADS, 1)
void vq_main(const float* __restrict__ residual,
             const float* __restrict__ cb,
             float* __restrict__ qout,
             float* __restrict__ codes,
             int N, int K, int wq, int wc)
{
    extern __shared__ __align__(16) unsigned char dsm[];
    const uint32_t sb = smem_u32(dsm);

    float*          sC2   = (float*)(dsm + OFF_C2);
    float*          sR2   = (float*)(dsm + OFF_R2);
    int*            sCNT  = (int*)(dsm + OFF_CNT);
    unsigned short* sCand = (unsigned short*)(dsm + OFF_CAND);

    const int tid  = threadIdx.x;
    const int lane = tid & 31;
    const int warp = tid >> 5;
    const int m0   = blockIdx.x * TM;
    const int rows = (N - m0 < TM) ? (N - m0) : TM;
    const int NT   = K >> 3;

    for (int i = tid; i < K; i += THREADS) sC2[i] = g_c2[i];

    // --- per-row: residual -> bf16 swizzled smem + exact r2 (R1 pattern) ---
    {
        const int r = tid;
        unsigned int* aU = reinterpret_cast<unsigned int*>(dsm + OFF_A) + r * 32;
        float r2 = 0.f;
        if (r < rows) {
            const float4* rr = reinterpret_cast<const float4*>(residual + (size_t)(m0 + r) * DIM);
            float p0 = 0.f, p1 = 0.f, p2 = 0.f, p3 = 0.f;
#pragma unroll
            for (int j = 0; j < 16; j++) {
                float4 v = rr[j];
                p0 += v.x * v.x;
                p1 += v.y * v.y;
                p2 += v.z * v.z;
                p3 += v.w * v.w;
                __nv_bfloat162 h0 = __floats2bfloat162_rn(v.x, v.y);
                __nv_bfloat162 h1 = __floats2bfloat162_rn(v.z, v.w);
                int j0 = 2 * j, j1 = 2 * j + 1;
                aU[(((j0 >> 2) ^ (r & 7)) << 2) + (j0 & 3)] = *reinterpret_cast<unsigned int*>(&h0);
                aU[(((j1 >> 2) ^ (r & 7)) << 2) + (j1 & 3)] = *reinterpret_cast<unsigned int*>(&h1);
            }
            r2 = (p0 + p1) + (p2 + p3);
        } else {
#pragma unroll
            for (int j = 0; j < 32; j++) aU[j] = 0;
        }
        sR2[r]  = r2;
        sCNT[r] = 0;
    }
    __syncthreads();

    // --- A fragments (resident): 2 m-tiles x 4 k-chunks, swizzled ldmatrix.x4 ---
    uint32_t a[2][4][4];
#pragma unroll
    for (int mt = 0; mt < 2; mt++) {
        const uint32_t rowb = (uint32_t)(warp * 32 + mt * 16 + (lane & 15)) * 128u;
#pragma unroll
        for (int kc = 0; kc < 4; kc++) {
            uint32_t phys = (uint32_t)((2 * kc + (lane >> 4)) ^ (lane & 7));
            uint32_t ad = sb + OFF_A + rowb + (phys << 4);
            asm volatile("ldmatrix.sync.aligned.m8n8.x4.shared.b16 {%0,%1,%2,%3}, [%4];"
                : "=r"(a[mt][kc][0]), "=r"(a[mt][kc][1]),
                  "=r"(a[mt][kc][2]), "=r"(a[mt][kc][3])
                : "r"(ad));
        }
    }

    const uint4* bp = g_cbFrag + lane;          // per-lane fragment stream
    const float* c2p = sC2 + ((lane & 3) << 1);
    const int rA0 = warp * 32 + (lane >> 2);    // slot rows: rA0, +8, +16, +24

    // ================= PASS A: per-row min of s~ = c2 - 2*dot~ =================
    float m00 = 3.0e38f, m01 = 3.0e38f;   // mt0: rows rA0, rA0+8
    float m10 = 3.0e38f, m11 = 3.0e38f;   // mt1: rows rA0+16, rA0+24
    {
        uint4 c0 = bp[0], c1 = bp[32];
        for (int nt = 0; nt < NT; nt++) {
            const int ntn = (nt + 1 < NT) ? nt + 1 : nt;
            uint4 n0 = bp[ntn * 64], n1 = bp[ntn * 64 + 32];
            const float2 c2v = *reinterpret_cast<const float2*>(c2p + (nt << 3));
            float s0, s1, s2, s3;
            MT_S(a[0]);
            m00 = fminf(m00, fminf(s0, s1));
            m01 = fminf(m01, fminf(s2, s3));
            MT_S(a[1]);
            m10 = fminf(m10, fminf(s0, s1));
            m11 = fminf(m11, fminf(s2, s3));
            c0 = n0; c1 = n1;
        }
    }

    // --- quad reduce + threshold -> per-slot limits ---
    const float CmaxC = __uint_as_float(g_cmaxU) * 0.018f;
    float lim00, lim01, lim10, lim11;
    {
        m00 = fminf(m00, __shfl_xor_sync(0xFFFFFFFFu, m00, 1));
        m00 = fminf(m00, __shfl_xor_sync(0xFFFFFFFFu, m00, 2));
        m01 = fminf(m01, __shfl_xor_sync(0xFFFFFFFFu, m01, 1));
        m01 = fminf(m01, __shfl_xor_sync(0xFFFFFFFFu, m01, 2));
        m10 = fminf(m10, __shfl_xor_sync(0xFFFFFFFFu, m10, 1));
        m10 = fminf(m10, __shfl_xor_sync(0xFFFFFFFFu, m10, 2));
        m11 = fminf(m11, __shfl_xor_sync(0xFFFFFFFFu, m11, 1));
        m11 = fminf(m11, __shfl_xor_sync(0xFFFFFFFFu, m11, 2));
        lim00 = m00 + (sqrtf(sR2[rA0])      * CmaxC + 5e-5f);
        lim01 = m01 + (sqrtf(sR2[rA0 + 8])  * CmaxC + 5e-5f);
        lim10 = m10 + (sqrtf(sR2[rA0 + 16]) * CmaxC + 5e-5f);
        lim11 = m11 + (sqrtf(sR2[rA0 + 24]) * CmaxC + 5e-5f);
    }

    // ================= PASS B: bitwise replay, collect s~ <= lim =================
    {
        uint4 c0 = bp[0], c1 = bp[32];
        for (int nt = 0; nt < NT; nt++) {
            const int ntn = (nt + 1 < NT) ? nt + 1 : nt;
            uint4 n0 = bp[ntn * 64], n1 = bp[ntn * 64 + 32];
            const float2 c2v = *reinterpret_cast<const float2*>(c2p + (nt << 3));
            const int colb = (nt << 3) + ((lane & 3) << 1);
            float s0, s1, s2, s3;
            MT_S(a[0]);
            if (fminf(s0, s1) <= lim00) {
                if (s0 <= lim00) APPEND(rA0, colb);
                if (s1 <= lim00) APPEND(rA0, colb + 1);
            }
            if (fminf(s2, s3) <= lim01) {
                if (s2 <= lim01) APPEND(rA0 + 8, colb);
                if (s3 <= lim01) APPEND(rA0 + 8, colb + 1);
            }
            MT_S(a[1]);
            if (fminf(s0, s1) <= lim10) {
                if (s0 <= lim10) APPEND(rA0 + 16, colb);
                if (s1 <= lim10) APPEND(rA0 + 16, colb + 1);
            }
            if (fminf(s2, s3) <= lim11) {
                if (s2 <= lim11) APPEND(rA0 + 24, colb);
                if (s3 <= lim11) APPEND(rA0 + 24, colb + 1);
            }
            c0 = n0; c1 = n1;
        }
    }
    __syncthreads();

    // ================= exact phase: R1-proven fp32 on candidate set =================
    const int t = tid;
    if (t < rows) {
        const int cn = sCNT[t];
        int bestK;
        if (cn == 1) {
            bestK = sCand[t * CAP];          // unique candidate: must be the argmin
        } else {
            const float r2 = sR2[t];
            float r[DIM];
            const float4* rr = reinterpret_cast<const float4*>(residual + (size_t)(m0 + t) * DIM);
#pragma unroll
            for (int j = 0; j < 16; j++) {
                float4 v = rr[j];
                r[4 * j + 0] = v.x; r[4 * j + 1] = v.y;
                r[4 * j + 2] = v.z; r[4 * j + 3] = v.w;
            }
            float best = 3.402823466e+38f;
            bestK = 0x7FFFFFFF;
            if (cn <= CAP) {
                for (int i = 0; i < cn; i++) {
                    int k = sCand[t * CAP + i];
                    const float4* c4 = reinterpret_cast<const float4*>(cb + (size_t)k * DIM);
                    float a0 = 0.f;
#pragma unroll
                    for (int j = 0; j < 16; j++) {
                        float4 v = c4[j];
                        a0 += r[4 * j + 0] * v.x;
                        a0 += r[4 * j + 1] * v.y;
                        a0 += r[4 * j + 2] * v.z;
                        a0 += r[4 * j + 3] * v.w;
                    }
                    float d = (r2 + sC2[k]) - 2.0f * a0;
                    if (d < best || (d == best && k < bestK)) { best = d; bestK = k; }
                }
            } else {
                for (int k = 0; k < K; k++) {      // overflow fallback (statistically never)
                    const float4* c4 = reinterpret_cast<const float4*>(cb + (size_t)k * DIM);
                    float a0 = 0.f;
#pragma unroll
                    for (int j = 0; j < 16; j++) {
                        float4 v = c4[j];
                        a0 += r[4 * j + 0] * v.x;
                        a0 += r[4 * j + 1] * v.y;
                        a0 += r[4 * j + 2] * v.z;
                        a0 += r[4 * j + 3] * v.w;
                    }
                    float d = (r2 + sC2[k]) - 2.0f * a0;
                    if (d < best) { best = d; bestK = k; }
                }
            }
        }
        const int n = m0 + t;
        if (wc) codes[n] = (float)bestK;
        if (wq) {
            const float4* brow = reinterpret_cast<const float4*>(cb + (size_t)bestK * DIM);
            float4* qo = reinterpret_cast<float4*>(qout + (size_t)n * DIM);
#pragma unroll
            for (int j = 0; j < 16; j++) qo[j] = brow[j];
        }
    }
}

// ---------------- launch ----------------
extern "C" void kernel_launch(void* const* d_in, const int* in_sizes, int n_in,
                              void* d_out, int out_size)
{
    const float* residual = (const float*)d_in[0];
    const float* cb       = (const float*)d_in[1];
    const int N = in_sizes[0] / DIM;
    const int K = in_sizes[1] / DIM;

    float* out = (float*)d_out;
    int write_q = 0, write_codes = 0;
    float* qout = out;
    float* codes = out;
    if (out_size >= N * DIM + N) {
        write_q = 1; write_codes = 1;
        codes = out + (size_t)N * DIM;
    } else if (out_size >= N * DIM) {
        write_q = 1;
    } else {
        write_codes = 1;
    }

    cudaFuncSetAttribute(vq_main, cudaFuncAttributeMaxDynamicSharedMemorySize, SMEM_DYN);

    prep_kernel<<<(K + 255) / 256, 256>>>(cb, K);

    int blocks = (N + TM - 1) / TM;
    vq_main<<<blocks, THREADS, SMEM_DYN>>>(residual, cb, qout, codes,
                                           N, K, write_q, write_codes);
}